// round 8
// baseline (speedup 1.0000x reference)
#include <cuda_runtime.h>
#include <cstdint>

// upfirdn2d, UP=1, DOWN=2, PAD=5, separable sym6 (12 taps), fp32.
// Phase V: vertical 12-tap stride-2 straight from global, LDG.128 column
// quads (4 cols/thread), 12-deep float4 register ring -> 2x bytes in flight
// per load slot vs float2. Phase H: horizontal 12-tap stride-2 from smem.

#define IMG_H   256
#define IMG_W   256
#define OUT_H   128
#define OUT_W   128
#define O_ROWS  64
#define STRIDE  276           // floats; 276 % 32 = 20 -> low-conflict phase H
#define PADL    8             // left zero pad; data words [8, 264)
#define NT      512

#define HR0  ( 0.015404109327027373f)
#define HR1  ( 0.0034907120842428036f == 0.0f ? 0.0f : 0.0034907120842174702f)
#define HR2  (-0.11799011114819057f)
#define HR3  (-0.048311742585633f)
#define HR4  ( 0.4910559419267466f)
#define HR5  ( 0.787641141030194f)
#define HR6  ( 0.3379294217276218f)
#define HR7  (-0.07263752278646252f)
#define HR8  (-0.021060292512300564f)
#define HR9  ( 0.04472490177066578f)
#define HR10 ( 0.0017677118642428036f)
#define HR11 (-0.007800708325034148f)

__device__ __forceinline__ float tap12(const float* w) {
    float a;
    a = HR0 * w[0];
    a = fmaf(HR1,  w[1],  a);
    a = fmaf(HR2,  w[2],  a);
    a = fmaf(HR3,  w[3],  a);
    a = fmaf(HR4,  w[4],  a);
    a = fmaf(HR5,  w[5],  a);
    a = fmaf(HR6,  w[6],  a);
    a = fmaf(HR7,  w[7],  a);
    a = fmaf(HR8,  w[8],  a);
    a = fmaf(HR9,  w[9],  a);
    a = fmaf(HR10, w[10], a);
    a = fmaf(HR11, w[11], a);
    return a;
}

__device__ __forceinline__ float4 tap12v4(const float4* w) {
    float4 a;
    a.x = HR0 * w[0].x;  a.y = HR0 * w[0].y;  a.z = HR0 * w[0].z;  a.w = HR0 * w[0].w;
#define ACC4(K, HK) \
    a.x = fmaf(HK, w[K].x, a.x); a.y = fmaf(HK, w[K].y, a.y); \
    a.z = fmaf(HK, w[K].z, a.z); a.w = fmaf(HK, w[K].w, a.w);
    ACC4(1, HR1)  ACC4(2, HR2)  ACC4(3, HR3)  ACC4(4, HR4)
    ACC4(5, HR5)  ACC4(6, HR6)  ACC4(7, HR7)  ACC4(8, HR8)
    ACC4(9, HR9)  ACC4(10, HR10) ACC4(11, HR11)
#undef ACC4
    return a;
}

// Vertical strip: 8 output rows x 4 columns. 12-deep float4 ring,
// 10-row preload burst. CHECK=false -> no bounds predicates.
template<bool CHECK>
__device__ __forceinline__ void vstrip(const float4* __restrict__ colp,
                                       float* __restrict__ sdst, int g0)
{
    float4 w[12];
    #pragma unroll
    for (int t = 0; t < 10; t++) {
        int g = g0 + t;
        if (CHECK && (unsigned)g >= (unsigned)IMG_H)
            w[t] = make_float4(0.f, 0.f, 0.f, 0.f);
        else
            w[t] = __ldg(colp + g * (IMG_W / 4));
    }
    #pragma unroll
    for (int i = 0; i < 8; i++) {
        int gA = g0 + 2 * i + 10;
        int gB = gA + 1;
        if (CHECK && (unsigned)gA >= (unsigned)IMG_H)
            w[10] = make_float4(0.f, 0.f, 0.f, 0.f);
        else
            w[10] = __ldg(colp + gA * (IMG_W / 4));
        if (CHECK && (unsigned)gB >= (unsigned)IMG_H)
            w[11] = make_float4(0.f, 0.f, 0.f, 0.f);
        else
            w[11] = __ldg(colp + gB * (IMG_W / 4));

        float4 o = tap12v4(w);
        *reinterpret_cast<float4*>(sdst + i * STRIDE) = o;

        #pragma unroll
        for (int k = 0; k < 10; k++) w[k] = w[k + 2];
    }
}

__global__ void __launch_bounds__(NT, 2)
hp_sym6_v6(const float* __restrict__ in, float* __restrict__ out)
{
    extern __shared__ float tmpV[];   // [O_ROWS][STRIDE]

    const int ty  = blockIdx.x;       // tile within image (fastest -> L2 halo reuse)
    const int img = blockIdx.y;
    const int tid = threadIdx.x;
    const int i0  = ty * O_ROWS;

    const float* __restrict__ src = in + (size_t)img * (IMG_H * IMG_W);

    // zero pad columns: words [0,8) and [264,276) of each tmpV row
    #pragma unroll
    for (int z = tid; z < O_ROWS * 20; z += NT) {
        int rr = z / 20;
        int pz = z - rr * 20;
        tmpV[rr * STRIDE + (pz < 8 ? pz : 256 + pz)] = 0.0f;
    }

    // ---- Phase V: 8 strips x 8 output rows; 4 columns (float4) per thread ----
    {
        const int cg = tid & 63;            // column quad 0..63 -> cols 4*cg..4*cg+3
        const int h  = tid >> 6;            // strip 0..7 (warp-uniform)
        const int r0 = h * 8;               // local output row of strip
        const int g0 = 2 * (i0 + r0) - 5;   // first input row (26 needed)

        const float4* colp = reinterpret_cast<const float4*>(src + 4 * cg);
        float* sdst = &tmpV[r0 * STRIDE + PADL + 4 * cg];

        if (g0 >= 0 && g0 + 25 < IMG_H) vstrip<false>(colp, sdst, g0);
        else                            vstrip<true >(colp, sdst, g0);
    }
    __syncthreads();

    // ---- Phase H: 12-tap stride-2 from smem, 16 outputs per thread ----
    {
        const int wid  = tid >> 5;          // 0..15
        const int lane = tid & 31;
        const int c8   = lane >> 2;         // 0..7 -> 16 output cols each
        const int isub = lane & 3;
        const int il   = 4 * wid + isub;    // local output row 0..63

        const float* rowv = &tmpV[il * STRIDE + 32 * c8];
        float v[48];
        #pragma unroll
        for (int m = 0; m < 12; m++) {
            float4 q = *reinterpret_cast<const float4*>(rowv + 4 * m);
            v[4 * m + 0] = q.x;
            v[4 * m + 1] = q.y;
            v[4 * m + 2] = q.z;
            v[4 * m + 3] = q.w;
        }

        float o[16];
        #pragma unroll
        for (int d = 0; d < 16; d++)
            o[d] = tap12(&v[2 * d + 3]);

        float* __restrict__ dst =
            out + (size_t)img * (OUT_H * OUT_W) + (i0 + il) * OUT_W + 16 * c8;
        #pragma unroll
        for (int s = 0; s < 4; s++) {
            float4 q = make_float4(o[4*s], o[4*s+1], o[4*s+2], o[4*s+3]);
            *reinterpret_cast<float4*>(dst + 4 * s) = q;
        }
    }
}

extern "C" void kernel_launch(void* const* d_in, const int* in_sizes, int n_in,
                              void* d_out, int out_size)
{
    const float* x = (const float*)d_in[0];
    float* y = (float*)d_out;

    int n_img = in_sizes[0] / (IMG_H * IMG_W);            // 1024
    size_t smem = (size_t)O_ROWS * STRIDE * sizeof(float); // 70656 B

    cudaFuncSetAttribute(hp_sym6_v6,
                         cudaFuncAttributeMaxDynamicSharedMemorySize, (int)smem);

    dim3 grid(OUT_H / O_ROWS, n_img);   // (2, 1024): tiles fastest for L2 reuse
    hp_sym6_v6<<<grid, NT, smem>>>(x, y);
}